// round 1
// baseline (speedup 1.0000x reference)
#include <cuda_runtime.h>

// Problem constants (z: [8192, 20, 256] f32, labels: [8192] i32, K=10)
#define NUM_LABELS 10
#define B_ROWS     8192
#define CH         5120          // C*H = 20*256
#define EPS        1e-8f

#define TPB            128       // threads per CTA in accumulate kernel
#define COLS_PER_CTA   512       // TPB * 4 (float4 per thread)
#define ROWS_PER_CHUNK 128
#define COL_BLOCKS     (CH / COLS_PER_CTA)          // 10
#define ROW_CHUNKS     (B_ROWS / ROWS_PER_CHUNK)    // 64

// Scratch (allocation-free: __device__ globals)
__device__ float g_sum [NUM_LABELS * CH];
__device__ float g_sum2[NUM_LABELS * CH];
__device__ int   g_rl  [B_ROWS];          // (row << 4) | label, grouped by label
__device__ int   g_counts[NUM_LABELS];

// ---------------------------------------------------------------------------
// Kernel Z: zero the accumulators (needed fresh on every graph replay)
// ---------------------------------------------------------------------------
__global__ void zero_kernel() {
    int n = NUM_LABELS * CH;
    for (int i = blockIdx.x * blockDim.x + threadIdx.x; i < n;
         i += gridDim.x * blockDim.x) {
        g_sum[i]  = 0.0f;
        g_sum2[i] = 0.0f;
    }
}

// ---------------------------------------------------------------------------
// Kernel A: counting-sort row indices by label (1 CTA).
// Warp-aggregated shared atomics keep contention tiny.
// ---------------------------------------------------------------------------
__global__ void sort_kernel(const int* __restrict__ labels) {
    __shared__ int sh_hist[NUM_LABELS];
    __shared__ int sh_off[NUM_LABELS];
    const int tid  = threadIdx.x;
    const int lane = tid & 31;

    if (tid < NUM_LABELS) sh_hist[tid] = 0;
    __syncthreads();

    // Histogram (B_ROWS % blockDim == 0 -> all lanes always active)
    for (int b = tid; b < B_ROWS; b += blockDim.x) {
        int lab = labels[b];
        unsigned mask = __match_any_sync(0xffffffffu, lab);
        int leader = __ffs(mask) - 1;
        if (lane == leader) atomicAdd(&sh_hist[lab], __popc(mask));
    }
    __syncthreads();

    if (tid == 0) {
        int acc = 0;
        for (int k = 0; k < NUM_LABELS; k++) { sh_off[k] = acc; acc += sh_hist[k]; }
    }
    if (tid < NUM_LABELS) g_counts[tid] = sh_hist[tid];
    __syncthreads();

    // Scatter: stable-enough grouping by label (order within group irrelevant)
    for (int b = tid; b < B_ROWS; b += blockDim.x) {
        int lab = labels[b];
        unsigned mask = __match_any_sync(0xffffffffu, lab);
        int leader = __ffs(mask) - 1;
        int rank   = __popc(mask & ((1u << lane) - 1u));
        int base = 0;
        if (lane == leader) base = atomicAdd(&sh_off[lab], __popc(mask));
        base = __shfl_sync(0xffffffffu, base, leader);
        g_rl[base + rank] = (b << 4) | lab;
    }
}

// ---------------------------------------------------------------------------
// Kernel B: one-pass segmented sum / sum-of-squares.
// grid = (COL_BLOCKS, ROW_CHUNKS), 128 threads, float4 per thread.
// Rows walked in label-sorted order -> register accumulators, rare flushes.
// ---------------------------------------------------------------------------
__device__ __forceinline__ void flush_acc(int lab, int colBase,
                                          float4& a, float4& a2) {
    int base = lab * CH + colBase;
    atomicAdd(&g_sum [base + 0], a.x);
    atomicAdd(&g_sum [base + 1], a.y);
    atomicAdd(&g_sum [base + 2], a.z);
    atomicAdd(&g_sum [base + 3], a.w);
    atomicAdd(&g_sum2[base + 0], a2.x);
    atomicAdd(&g_sum2[base + 1], a2.y);
    atomicAdd(&g_sum2[base + 2], a2.z);
    atomicAdd(&g_sum2[base + 3], a2.w);
    a  = make_float4(0.f, 0.f, 0.f, 0.f);
    a2 = make_float4(0.f, 0.f, 0.f, 0.f);
}

__global__ __launch_bounds__(TPB) void accum_kernel(const float* __restrict__ z) {
    __shared__ int s_rl[ROWS_PER_CHUNK];
    const int tid = threadIdx.x;
    const int cb  = blockIdx.x;   // column block 0..9
    const int rc  = blockIdx.y;   // row chunk   0..63

    s_rl[tid] = g_rl[rc * ROWS_PER_CHUNK + tid];
    __syncthreads();

    const float4* __restrict__ z4 = (const float4*)z;
    const int col4    = cb * (COLS_PER_CTA / 4) + tid;   // float4 index in row
    const int colBase = cb * COLS_PER_CTA + tid * 4;     // scalar column base

    float4 a  = make_float4(0.f, 0.f, 0.f, 0.f);
    float4 a2 = make_float4(0.f, 0.f, 0.f, 0.f);
    int cur = s_rl[0] & 15;

    for (int i = 0; i < ROWS_PER_CHUNK; i += 4) {
        // 4 independent loads up front -> MLP=4 per thread
        const int rl0 = s_rl[i + 0], rl1 = s_rl[i + 1];
        const int rl2 = s_rl[i + 2], rl3 = s_rl[i + 3];
        float4 v0 = z4[(rl0 >> 4) * (CH / 4) + col4];
        float4 v1 = z4[(rl1 >> 4) * (CH / 4) + col4];
        float4 v2 = z4[(rl2 >> 4) * (CH / 4) + col4];
        float4 v3 = z4[(rl3 >> 4) * (CH / 4) + col4];

        int lab;
        lab = rl0 & 15;
        if (lab != cur) { flush_acc(cur, colBase, a, a2); cur = lab; }
        a.x += v0.x; a.y += v0.y; a.z += v0.z; a.w += v0.w;
        a2.x = fmaf(v0.x, v0.x, a2.x); a2.y = fmaf(v0.y, v0.y, a2.y);
        a2.z = fmaf(v0.z, v0.z, a2.z); a2.w = fmaf(v0.w, v0.w, a2.w);

        lab = rl1 & 15;
        if (lab != cur) { flush_acc(cur, colBase, a, a2); cur = lab; }
        a.x += v1.x; a.y += v1.y; a.z += v1.z; a.w += v1.w;
        a2.x = fmaf(v1.x, v1.x, a2.x); a2.y = fmaf(v1.y, v1.y, a2.y);
        a2.z = fmaf(v1.z, v1.z, a2.z); a2.w = fmaf(v1.w, v1.w, a2.w);

        lab = rl2 & 15;
        if (lab != cur) { flush_acc(cur, colBase, a, a2); cur = lab; }
        a.x += v2.x; a.y += v2.y; a.z += v2.z; a.w += v2.w;
        a2.x = fmaf(v2.x, v2.x, a2.x); a2.y = fmaf(v2.y, v2.y, a2.y);
        a2.z = fmaf(v2.z, v2.z, a2.z); a2.w = fmaf(v2.w, v2.w, a2.w);

        lab = rl3 & 15;
        if (lab != cur) { flush_acc(cur, colBase, a, a2); cur = lab; }
        a.x += v3.x; a.y += v3.y; a.z += v3.z; a.w += v3.w;
        a2.x = fmaf(v3.x, v3.x, a2.x); a2.y = fmaf(v3.y, v3.y, a2.y);
        a2.z = fmaf(v3.z, v3.z, a2.z); a2.w = fmaf(v3.w, v3.w, a2.w);
    }
    flush_acc(cur, colBase, a, a2);
}

// ---------------------------------------------------------------------------
// Kernel C: finalize.  sse(k,j) = q - 2*m'*s + n*m'^2, m' = s/n - EPS.
// total = sum_k [ sum_j sse(k,j) ] / (n_k * CH),  for n_k > 0.
// ---------------------------------------------------------------------------
__global__ void finalize_kernel(float* __restrict__ out) {
    __shared__ float sh[32];
    const int tid = threadIdx.x;
    float acc = 0.0f;

    for (int idx = tid; idx < NUM_LABELS * CH; idx += blockDim.x) {
        int k = idx / CH;
        float n = (float)g_counts[k];
        if (n > 0.0f) {
            float s = g_sum[idx];
            float q = g_sum2[idx];
            float mp = s / n - EPS;
            float e  = q - 2.0f * mp * s + n * mp * mp;
            acc += e / (n * (float)CH);
        }
    }
    #pragma unroll
    for (int o = 16; o > 0; o >>= 1) acc += __shfl_down_sync(0xffffffffu, acc, o);
    if ((tid & 31) == 0) sh[tid >> 5] = acc;
    __syncthreads();
    if (tid < 32) {
        float v = (tid < (int)(blockDim.x >> 5)) ? sh[tid] : 0.0f;
        #pragma unroll
        for (int o = 16; o > 0; o >>= 1) v += __shfl_down_sync(0xffffffffu, v, o);
        if (tid == 0) out[0] = v;
    }
}

// ---------------------------------------------------------------------------
extern "C" void kernel_launch(void* const* d_in, const int* in_sizes, int n_in,
                              void* d_out, int out_size) {
    const float* z      = (const float*)d_in[0];
    const int*   labels = (const int*)d_in[1];
    (void)in_sizes; (void)n_in; (void)out_size;

    zero_kernel<<<160, 256>>>();
    sort_kernel<<<1, 256>>>(labels);
    accum_kernel<<<dim3(COL_BLOCKS, ROW_CHUNKS), TPB>>>(z);
    finalize_kernel<<<1, 1024>>>((float*)d_out);
}

// round 2
// speedup vs baseline: 1.8722x; 1.8722x over previous
#include <cuda_runtime.h>

// Problem constants (z: [8192, 20, 256] f32, labels: [8192] i32, K=10)
#define NUM_LABELS 10
#define B_ROWS     8192
#define CH         5120          // C*H = 20*256
#define EPS        1e-8f

#define TPB            128       // threads per CTA in accumulate kernel
#define COLS_PER_CTA   512       // TPB * 4 (float4 per thread)
#define ROWS_PER_CHUNK 128
#define COL_BLOCKS     (CH / COLS_PER_CTA)          // 10
#define ROW_CHUNKS     (B_ROWS / ROWS_PER_CHUNK)    // 64

// Scratch (allocation-free: __device__ globals)
__device__ float g_sum [NUM_LABELS * CH];
__device__ float g_sum2[NUM_LABELS * CH];
__device__ int   g_rl  [B_ROWS];          // (row << 4) | label, grouped by label
__device__ int   g_counts[NUM_LABELS];

// ---------------------------------------------------------------------------
// Kernel Z: zero accumulators + the output scalar (fresh every graph replay)
// ---------------------------------------------------------------------------
__global__ void zero_kernel(float* __restrict__ out) {
    int n = NUM_LABELS * CH;
    int i0 = blockIdx.x * blockDim.x + threadIdx.x;
    for (int i = i0; i < n; i += gridDim.x * blockDim.x) {
        g_sum[i]  = 0.0f;
        g_sum2[i] = 0.0f;
    }
    if (i0 == 0) out[0] = 0.0f;
}

// ---------------------------------------------------------------------------
// Kernel A: counting-sort row indices by label (1 CTA, 1024 thr, int4 loads)
// ---------------------------------------------------------------------------
__global__ __launch_bounds__(1024) void sort_kernel(const int* __restrict__ labels) {
    __shared__ int sh_hist[NUM_LABELS];
    __shared__ int sh_off[NUM_LABELS];
    const int tid  = threadIdx.x;
    const int lane = tid & 31;
    const int4* __restrict__ lab4 = (const int4*)labels;

    if (tid < NUM_LABELS) sh_hist[tid] = 0;
    __syncthreads();

    // Histogram: 8192 labels = 2048 int4, 1024 threads -> 2 iterations
    #pragma unroll
    for (int it = 0; it < (B_ROWS / 4) / 1024; it++) {
        int4 v = lab4[it * 1024 + tid];
        #pragma unroll
        for (int j = 0; j < 4; j++) {
            int lab = (j == 0) ? v.x : (j == 1) ? v.y : (j == 2) ? v.z : v.w;
            unsigned mask = __match_any_sync(0xffffffffu, lab);
            if (lane == (__ffs(mask) - 1)) atomicAdd(&sh_hist[lab], __popc(mask));
        }
    }
    __syncthreads();

    if (tid == 0) {
        int acc = 0;
        #pragma unroll
        for (int k = 0; k < NUM_LABELS; k++) { sh_off[k] = acc; acc += sh_hist[k]; }
    }
    if (tid < NUM_LABELS) g_counts[tid] = sh_hist[tid];
    __syncthreads();

    // Scatter (order within a group is irrelevant)
    #pragma unroll
    for (int it = 0; it < (B_ROWS / 4) / 1024; it++) {
        int4 v = lab4[it * 1024 + tid];
        int b0 = (it * 1024 + tid) * 4;
        #pragma unroll
        for (int j = 0; j < 4; j++) {
            int lab = (j == 0) ? v.x : (j == 1) ? v.y : (j == 2) ? v.z : v.w;
            unsigned mask = __match_any_sync(0xffffffffu, lab);
            int leader = __ffs(mask) - 1;
            int rank   = __popc(mask & ((1u << lane) - 1u));
            int base = 0;
            if (lane == leader) base = atomicAdd(&sh_off[lab], __popc(mask));
            base = __shfl_sync(0xffffffffu, base, leader);
            g_rl[base + rank] = ((b0 + j) << 4) | lab;
        }
    }
}

// ---------------------------------------------------------------------------
// Kernel B: one-pass segmented sum / sum-of-squares.
// grid = (COL_BLOCKS, ROW_CHUNKS), 128 threads, float4/thread, 8-deep MLP.
// ---------------------------------------------------------------------------
__device__ __forceinline__ void flush_acc(int lab, int colBase,
                                          float4& a, float4& a2) {
    int base = lab * CH + colBase;
    atomicAdd(&g_sum [base + 0], a.x);
    atomicAdd(&g_sum [base + 1], a.y);
    atomicAdd(&g_sum [base + 2], a.z);
    atomicAdd(&g_sum [base + 3], a.w);
    atomicAdd(&g_sum2[base + 0], a2.x);
    atomicAdd(&g_sum2[base + 1], a2.y);
    atomicAdd(&g_sum2[base + 2], a2.z);
    atomicAdd(&g_sum2[base + 3], a2.w);
    a  = make_float4(0.f, 0.f, 0.f, 0.f);
    a2 = make_float4(0.f, 0.f, 0.f, 0.f);
}

__global__ __launch_bounds__(TPB) void accum_kernel(const float* __restrict__ z) {
    __shared__ int s_rl[ROWS_PER_CHUNK];
    const int tid = threadIdx.x;
    const int cb  = blockIdx.x;   // column block 0..9
    const int rc  = blockIdx.y;   // row chunk   0..63

    s_rl[tid] = g_rl[rc * ROWS_PER_CHUNK + tid];
    __syncthreads();

    const float4* __restrict__ z4 = (const float4*)z;
    const int col4    = cb * (COLS_PER_CTA / 4) + tid;   // float4 index in row
    const int colBase = cb * COLS_PER_CTA + tid * 4;     // scalar column base

    float4 a  = make_float4(0.f, 0.f, 0.f, 0.f);
    float4 a2 = make_float4(0.f, 0.f, 0.f, 0.f);
    int cur = s_rl[0] & 15;

    for (int i = 0; i < ROWS_PER_CHUNK; i += 8) {
        // 8 independent loads issued up front -> MLP=8 per thread
        int   rl[8];
        float4 v[8];
        #pragma unroll
        for (int u = 0; u < 8; u++) rl[u] = s_rl[i + u];
        #pragma unroll
        for (int u = 0; u < 8; u++) v[u] = z4[(rl[u] >> 4) * (CH / 4) + col4];

        #pragma unroll
        for (int u = 0; u < 8; u++) {
            int lab = rl[u] & 15;
            if (lab != cur) { flush_acc(cur, colBase, a, a2); cur = lab; }
            a.x += v[u].x; a.y += v[u].y; a.z += v[u].z; a.w += v[u].w;
            a2.x = fmaf(v[u].x, v[u].x, a2.x);
            a2.y = fmaf(v[u].y, v[u].y, a2.y);
            a2.z = fmaf(v[u].z, v[u].z, a2.z);
            a2.w = fmaf(v[u].w, v[u].w, a2.w);
        }
    }
    flush_acc(cur, colBase, a, a2);
}

// ---------------------------------------------------------------------------
// Kernel C: finalize, parallel.  grid = (NUM_LABELS, CH/256), 256 thr.
// Each thread handles one (k, j) cell; CTA-reduce; atomicAdd into out[0].
// sse(k,j) = q - 2*m'*s + n*m'^2, with m' = s/n - EPS.
// ---------------------------------------------------------------------------
__global__ __launch_bounds__(256) void finalize_kernel(float* __restrict__ out) {
    __shared__ float sh[8];
    const int k   = blockIdx.x;
    const int j   = blockIdx.y * 256 + threadIdx.x;
    const int tid = threadIdx.x;

    float n = (float)g_counts[k];
    float acc = 0.0f;
    if (n > 0.0f) {
        int idx  = k * CH + j;
        float s  = g_sum[idx];
        float q  = g_sum2[idx];
        float mp = s / n - EPS;
        float e  = q - 2.0f * mp * s + n * mp * mp;
        acc = e / (n * (float)CH);
    }
    #pragma unroll
    for (int o = 16; o > 0; o >>= 1) acc += __shfl_down_sync(0xffffffffu, acc, o);
    if ((tid & 31) == 0) sh[tid >> 5] = acc;
    __syncthreads();
    if (tid < 8) {
        float v = sh[tid];
        #pragma unroll
        for (int o = 4; o > 0; o >>= 1) v += __shfl_down_sync(0xffu, v, o);
        if (tid == 0) atomicAdd(out, v);
    }
}

// ---------------------------------------------------------------------------
extern "C" void kernel_launch(void* const* d_in, const int* in_sizes, int n_in,
                              void* d_out, int out_size) {
    const float* z      = (const float*)d_in[0];
    const int*   labels = (const int*)d_in[1];
    (void)in_sizes; (void)n_in; (void)out_size;

    zero_kernel<<<160, 256>>>((float*)d_out);
    sort_kernel<<<1, 1024>>>(labels);
    accum_kernel<<<dim3(COL_BLOCKS, ROW_CHUNKS), TPB>>>(z);
    finalize_kernel<<<dim3(NUM_LABELS, CH / 256), 256>>>((float*)d_out);
}